// round 14
// baseline (speedup 1.0000x reference)
#include <cuda_runtime.h>
#include <cuda_fp16.h>
#include <cstdint>

// Problem constants
#define BB 512
#define SS 512
#define CC 32
#define DD 512
#define EE 8
#define EMBW 32

// ---------------------------------------------------------------------------
// Scratch (device globals — no allocation allowed)
// ---------------------------------------------------------------------------
__device__ __half g_Ah[DD * SS];        // Wmix^T fp16  [d][s] K-major
__device__ __half g_Xh[BB * CC * SS];   // xn fp16 [n=(b,v)][s] K-major

// ---------------------------------------------------------------------------
// helpers
// ---------------------------------------------------------------------------
__device__ __forceinline__ uint32_t smem_u32(const void* p) {
    uint32_t a;
    asm("{ .reg .u64 t; cvta.to.shared.u64 t, %1; cvt.u32.u64 %0, t; }"
        : "=r"(a) : "l"(p));
    return a;
}
__device__ __forceinline__ void cp_async16(uint32_t dst_smem, const void* src) {
    asm volatile("cp.async.cg.shared.global [%0], [%1], 16;"
                 :: "r"(dst_smem), "l"(src));
}
__device__ __forceinline__ void ldsm4(uint32_t* r, uint32_t addr) {
    asm volatile("ldmatrix.sync.aligned.m8n8.x4.shared.b16 {%0,%1,%2,%3}, [%4];"
                 : "=r"(r[0]), "=r"(r[1]), "=r"(r[2]), "=r"(r[3]) : "r"(addr));
}
__device__ __forceinline__ void mma_fp16(float* d, const uint32_t* a,
                                         uint32_t b0, uint32_t b1) {
    asm volatile(
        "mma.sync.aligned.m16n8k16.row.col.f32.f16.f16.f32 "
        "{%0,%1,%2,%3}, {%4,%5,%6,%7}, {%8,%9}, {%0,%1,%2,%3};"
        : "+f"(d[0]), "+f"(d[1]), "+f"(d[2]), "+f"(d[3])
        : "r"(a[0]), "r"(a[1]), "r"(a[2]), "r"(a[3]), "r"(b0), "r"(b1));
}
__device__ __forceinline__ unsigned f2ord(float f) {
    unsigned raw = __float_as_uint(f);
    return (raw & 0x80000000u) ? ~raw : (raw | 0x80000000u);
}
__device__ __forceinline__ float ord2f(unsigned u) {
    return (u & 0x80000000u) ? __uint_as_float(u ^ 0x80000000u)
                             : __uint_as_float(~u);
}

// ---------------------------------------------------------------------------
// Exact median of 512 values (u[16] per lane, ord space) via interpolation
// select: CDF-interpolated pivot counting to bracket ranks 256/257
// (1-indexed), then successive warp-min extraction with multiplicity.
// Exact for arbitrary inputs; fast for smooth distributions.
// ---------------------------------------------------------------------------
__device__ __forceinline__ float warp_median512(const unsigned* u) {
    const int K1 = 256, K2 = 257;            // 1-indexed target ranks

    // bracket init: [min, max+1)
    unsigned mn16 = 0xFFFFFFFFu, mx16 = 0u;
    #pragma unroll
    for (int r = 0; r < 16; r++) {
        mn16 = (u[r] < mn16) ? u[r] : mn16;
        mx16 = (u[r] > mx16) ? u[r] : mx16;
    }
    unsigned plo = __reduce_min_sync(0xFFFFFFFFu, mn16);
    unsigned phi = __reduce_max_sync(0xFFFFFFFFu, mx16) + 1u;
    int clo = 0, chi = 512;                  // counts of (u < p) at brackets
    float flo = ord2f(plo), fhi = ord2f(phi - 1u);

    // bracket loop: shrink candidate count between brackets
    for (int iter = 0; iter < 48 && (chi - clo) > 6 && (phi - plo) > 1u; iter++) {
        float t = (float)(K1 - clo) / (float)(chi - clo);
        float fp = flo + t * (fhi - flo);
        unsigned p = f2ord(fp);
        if (p <= plo || p >= phi)            // interpolation stalled: ord midpoint
            p = plo + ((phi - plo) >> 1);
        int cnt16 = 0;
        #pragma unroll
        for (int r = 0; r < 16; r++) cnt16 += (u[r] < p) ? 1 : 0;
        int c = __reduce_add_sync(0xFFFFFFFFu, cnt16);
        if (c >= K1) { phi = p; chi = c; fhi = ord2f(p - 1u); }
        else         { plo = p; clo = c; flo = ord2f(p); }
    }

    // extraction: successive minima of {u >= plo}, rank pointer r0 = clo
    int r0 = clo;
    unsigned cur = plo;
    unsigned v1o = 0, v2o = 0;
    while (true) {
        unsigned m16 = 0xFFFFFFFFu;
        #pragma unroll
        for (int r = 0; r < 16; r++)
            m16 = (u[r] >= cur && u[r] < m16) ? u[r] : m16;
        unsigned m = __reduce_min_sync(0xFFFFFFFFu, m16);
        int e16 = 0;
        #pragma unroll
        for (int r = 0; r < 16; r++) e16 += (u[r] == m) ? 1 : 0;
        int cnt = __reduce_add_sync(0xFFFFFFFFu, e16);
        if (r0 < K1 && r0 + cnt >= K1) v1o = m;
        if (r0 < K2 && r0 + cnt >= K2) { v2o = m; break; }
        r0 += cnt;
        cur = m + 1u;
    }
    return 0.5f * (ord2f(v1o) + ord2f(v2o));
}

// ---------------------------------------------------------------------------
// K1: prep_w — gate inline (logits separable => gates identical across
// batch), then A[d][s] = g1*We[e1][s][d] + g2*We[e2][s][d], fp16, K-major.
// 32x32 smem transpose tiles.  (Measured 6.0-6.2 us, R8-R11.)
// ---------------------------------------------------------------------------
__global__ void prep_w(const float* __restrict__ We,
                       const float* __restrict__ emb,
                       const float* __restrict__ Wg) {
    __shared__ float tile[32][33];
    __shared__ float s_g1, s_g2;
    __shared__ int s_e1, s_e2;

    int tx = threadIdx.x, ty = threadIdx.y;   // 32 x 8
    if (ty == 0) {
        int lane = tx;
        float t = -1e30f;
        if (lane < EE) {
            float s = 0.f;
            #pragma unroll
            for (int j = 0; j < EMBW; j++) s += emb[lane * EMBW + j] * Wg[DD + j];
            t = s;
        }
        float best = -1e30f, second = -1e30f;
        int be = 0, se = 0;
        #pragma unroll
        for (int e = 0; e < EE; e++) {
            float te = __shfl_sync(0xFFFFFFFFu, t, e);
            if (te > best)        { second = best; se = be; best = te; be = e; }
            else if (te > second) { second = te; se = e; }
        }
        if (lane == 0) {
            float e2 = expf(second - best);
            float inv = 1.0f / (1.0f + e2);
            s_g1 = inv;
            s_g2 = e2 * inv;
            s_e1 = be;
            s_e2 = se;
        }
    }
    __syncthreads();

    int s0 = blockIdx.x * 32, d0 = blockIdx.y * 32;
    float g1 = s_g1, g2 = s_g2;
    const float* A1 = We + (size_t)s_e1 * SS * DD;
    const float* A2 = We + (size_t)s_e2 * SS * DD;
    #pragma unroll
    for (int i = 0; i < 4; i++) {
        int s = s0 + ty + i * 8;
        tile[ty + i * 8][tx] =
            g1 * A1[(size_t)s * DD + d0 + tx] + g2 * A2[(size_t)s * DD + d0 + tx];
    }
    __syncthreads();
    #pragma unroll
    for (int i = 0; i < 4; i++) {
        int d = d0 + ty + i * 8;
        g_Ah[(size_t)d * SS + s0 + tx] = __float2half_rn(tile[tx][ty + i * 8]);
    }
}

// ---------------------------------------------------------------------------
// K2: prep_x — R7 structure (1024 blocks x 512 thr, 1 warp/channel) with
// interpolation-select exact median + subtract + fp16 + K-major transpose.
// ---------------------------------------------------------------------------
__global__ void __launch_bounds__(512) prep_x(const float* __restrict__ x) {
    __shared__ float sm[16 * 513];
    int b = blockIdx.x >> 1;
    int half = blockIdx.x & 1;
    const float4* xb4 = (const float4*)(x + (size_t)b * SS * CC + half * 16);

    for (int i = threadIdx.x; i < 512 * 4; i += 512) {
        int s = i >> 2, q = i & 3;
        float4 v = xb4[s * 8 + q];
        sm[(q * 4 + 0) * 513 + s] = v.x;
        sm[(q * 4 + 1) * 513 + s] = v.y;
        sm[(q * 4 + 2) * 513 + s] = v.z;
        sm[(q * 4 + 3) * 513 + s] = v.w;
    }
    __syncthreads();

    int w = threadIdx.x >> 5;
    int lane = threadIdx.x & 31;

    unsigned u[16];
    #pragma unroll
    for (int r = 0; r < 16; r++)
        u[r] = f2ord(sm[w * 513 + lane + 32 * r]);

    float med = warp_median512(u);

    int c = half * 16 + w;
    __half* dsth = g_Xh + (size_t)(b * CC + c) * SS;
    #pragma unroll
    for (int r = 0; r < 8; r++) {
        int s = r * 64 + lane * 2;
        float a0 = sm[w * 513 + s]     - med;
        float a1 = sm[w * 513 + s + 1] - med;
        *reinterpret_cast<__half2*>(dsth + s) = __floats2half2_rn(a0, a1);
    }
}

// ---------------------------------------------------------------------------
// K3: single-pass fp16 mma.sync GEMM — byte-exact R7/R12 configuration
// (measured 39.3-39.8 us).  Grid = 128 CTAs (4 m-tiles x 32 n-groups),
// 256 thr (8 warps), warp 32x64, KC=64, 4-stage cp.async pipeline,
// prefetch distance 3, continuous stream across the CTA's 4 n-tiles.
// ---------------------------------------------------------------------------
#define CTA_M 128
#define CTA_N 128
#define KC 64
#define NCH (SS / KC)            // 8 chunks per n-tile
#define NTPC 4                   // n-tiles per CTA
#define NIT (NTPC * NCH)         // 32 flat iterations
#define STG_BYTES 32768          // Ah 16K | Bh 16K
#define OFF_AH 0
#define OFF_BH 16384
#define NSTG 4
#define GSMEM (NSTG * STG_BYTES) // 131072

__global__ void __launch_bounds__(256) gemm_kernel(float* __restrict__ out) {
    extern __shared__ char smem[];
    uint32_t sb = smem_u32(smem);
    int tid = threadIdx.x;
    int lane = tid & 31, wid = tid >> 5;
    int wm = wid & 3;            // 4 m-groups of 32
    int wn = wid >> 2;           // 2 n-groups of 64
    int m0 = (blockIdx.x & 3) * CTA_M;
    int ng = blockIdx.x >> 2;    // n-group: tiles ng*4 .. ng*4+3

    const char* gA = (const char*)(g_Ah + (size_t)m0 * SS);
    const char* gB = (const char*)g_Xh;

    auto ldchunk = [&](int stage, int it) {
        uint32_t tb = sb + stage * STG_BYTES;
        int u = it >> 3, ck = it & 7;
        size_t nrow0 = (size_t)(ng * NTPC + u) * CTA_N;
        size_t kb = (size_t)ck * (KC * 2);
        #pragma unroll
        for (int t = 0; t < 4; t++) {
            int idx = tid + t * 256;
            int r = idx >> 3, c = idx & 7;
            uint32_t so = (uint32_t)(r * 128 + ((c * 16) ^ ((r & 7) << 4)));
            size_t goA = (size_t)r * (SS * 2) + kb + c * 16;
            size_t goB = (nrow0 + r) * (SS * 2) + kb + c * 16;
            cp_async16(tb + OFF_AH + so, gA + goA);
            cp_async16(tb + OFF_BH + so, gB + goB);
        }
        asm volatile("cp.async.commit_group;" ::: "memory");
    };

    ldchunk(0, 0);
    ldchunk(1, 1);
    ldchunk(2, 2);

    float acc[2][8][4];
    int r8 = lane & 7;
    int half8 = ((lane >> 3) & 1) * 8;
    int kh16 = (lane >> 4) * 16;

    for (int it = 0; it < NIT; it++) {
        // group for 'it' complete; it+1, it+2 may remain outstanding
        asm volatile("cp.async.wait_group 2;" ::: "memory");
        __syncthreads();

        // stage (it+3)%4 == (it-1)%4 is free after the sync above
        if (it + 3 < NIT) ldchunk((it + 3) % NSTG, it + 3);
        else asm volatile("cp.async.commit_group;" ::: "memory");

        if ((it & 7) == 0) {
            #pragma unroll
            for (int i = 0; i < 2; i++)
                #pragma unroll
                for (int j = 0; j < 8; j++)
                    #pragma unroll
                    for (int q = 0; q < 4; q++) acc[i][j][q] = 0.f;
        }

        uint32_t tb = sb + (it % NSTG) * STG_BYTES;
        #pragma unroll
        for (int ks = 0; ks < 4; ks++) {
            int kb0 = ks * 32 + kh16;
            uint32_t a[2][4], bfr[4][4];
            #pragma unroll
            for (int mb = 0; mb < 2; mb++) {
                int row = wm * 32 + mb * 16 + half8 + r8;
                uint32_t ad = (uint32_t)(row * 128 + (kb0 ^ ((row & 7) << 4)));
                ldsm4(a[mb], tb + OFF_AH + ad);
            }
            #pragma unroll
            for (int nb2 = 0; nb2 < 4; nb2++) {
                int row = wn * 64 + nb2 * 16 + half8 + r8;
                uint32_t ad = (uint32_t)(row * 128 + (kb0 ^ ((row & 7) << 4)));
                ldsm4(bfr[nb2], tb + OFF_BH + ad);
            }
            #pragma unroll
            for (int mb = 0; mb < 2; mb++)
                #pragma unroll
                for (int nb2 = 0; nb2 < 4; nb2++)
                    #pragma unroll
                    for (int s = 0; s < 2; s++)
                        mma_fp16(acc[mb][nb2 * 2 + s], a[mb],
                                 bfr[nb2][s], bfr[nb2][s + 2]);
        }

        if ((it & 7) == 7) {
            int u = it >> 3;
            int nbase = (ng * NTPC + u) * CTA_N + wn * 64;
            #pragma unroll
            for (int mb = 0; mb < 2; mb++) {
                int dr = m0 + wm * 32 + mb * 16 + (lane >> 2);
                #pragma unroll
                for (int nb8 = 0; nb8 < 8; nb8++) {
                    int bidx = (nbase >> 5) + (nb8 >> 2);
                    int v = (nb8 & 3) * 8 + 2 * (lane & 3);
                    float* ob = out + (size_t)bidx * DD * CC;
                    *(float2*)(ob + (size_t)dr * CC + v) =
                        make_float2(acc[mb][nb8][0], acc[mb][nb8][1]);
                    *(float2*)(ob + (size_t)(dr + 8) * CC + v) =
                        make_float2(acc[mb][nb8][2], acc[mb][nb8][3]);
                }
            }
        }
    }
}

// ---------------------------------------------------------------------------
// Launch.  Inputs: x, Wp, bp, emb, Wg, bg, We, k  (Wp/bp/bg/k provably unused)
// ---------------------------------------------------------------------------
extern "C" void kernel_launch(void* const* d_in, const int* in_sizes, int n_in,
                              void* d_out, int out_size) {
    const float* x   = (const float*)d_in[0];
    const float* emb = (const float*)d_in[3];
    const float* Wg  = (const float*)d_in[4];
    const float* We  = (const float*)d_in[6];
    float* out = (float*)d_out;

    cudaFuncSetAttribute(gemm_kernel,
                         cudaFuncAttributeMaxDynamicSharedMemorySize, GSMEM);

    prep_w<<<dim3(16, 16), dim3(32, 8)>>>(We, emb, Wg);
    prep_x<<<BB * 2, 512>>>(x);
    gemm_kernel<<<128, 256, GSMEM>>>(out);
}

// round 15
// speedup vs baseline: 1.3731x; 1.3731x over previous
#include <cuda_runtime.h>
#include <cuda_fp16.h>
#include <cstdint>

// Problem constants
#define BB 512
#define SS 512
#define CC 32
#define DD 512
#define EE 8
#define EMBW 32

// ---------------------------------------------------------------------------
// Scratch (device globals — no allocation allowed)
// ---------------------------------------------------------------------------
__device__ __half g_Ah[DD * SS];        // Wmix^T fp16  [d][s] K-major
__device__ __half g_Xh[BB * CC * SS];   // xn fp16 [n=(b,v)][s] K-major

// ---------------------------------------------------------------------------
// helpers
// ---------------------------------------------------------------------------
__device__ __forceinline__ uint32_t smem_u32(const void* p) {
    uint32_t a;
    asm("{ .reg .u64 t; cvta.to.shared.u64 t, %1; cvt.u32.u64 %0, t; }"
        : "=r"(a) : "l"(p));
    return a;
}
__device__ __forceinline__ void cp_async16(uint32_t dst_smem, const void* src) {
    asm volatile("cp.async.cg.shared.global [%0], [%1], 16;"
                 :: "r"(dst_smem), "l"(src));
}
__device__ __forceinline__ void ldsm4(uint32_t* r, uint32_t addr) {
    asm volatile("ldmatrix.sync.aligned.m8n8.x4.shared.b16 {%0,%1,%2,%3}, [%4];"
                 : "=r"(r[0]), "=r"(r[1]), "=r"(r[2]), "=r"(r[3]) : "r"(addr));
}
__device__ __forceinline__ void mma_fp16(float* d, const uint32_t* a,
                                         uint32_t b0, uint32_t b1) {
    asm volatile(
        "mma.sync.aligned.m16n8k16.row.col.f32.f16.f16.f32 "
        "{%0,%1,%2,%3}, {%4,%5,%6,%7}, {%8,%9}, {%0,%1,%2,%3};"
        : "+f"(d[0]), "+f"(d[1]), "+f"(d[2]), "+f"(d[3])
        : "r"(a[0]), "r"(a[1]), "r"(a[2]), "r"(a[3]), "r"(b0), "r"(b1));
}
__device__ __forceinline__ unsigned f2ord(float f) {
    unsigned raw = __float_as_uint(f);
    return (raw & 0x80000000u) ? ~raw : (raw | 0x80000000u);
}
__device__ __forceinline__ float ord2f(unsigned u) {
    return (u & 0x80000000u) ? __uint_as_float(u ^ 0x80000000u)
                             : __uint_as_float(~u);
}

// ---------------------------------------------------------------------------
// K1: prep_w — gate inline (logits separable => gates identical across
// batch), then A[d][s] = g1*We[e1][s][d] + g2*We[e2][s][d], fp16, K-major.
// 32x32 smem transpose tiles.  (Measured 6.0-6.2 us, R8-R11/R14.)
// ---------------------------------------------------------------------------
__global__ void prep_w(const float* __restrict__ We,
                       const float* __restrict__ emb,
                       const float* __restrict__ Wg) {
    __shared__ float tile[32][33];
    __shared__ float s_g1, s_g2;
    __shared__ int s_e1, s_e2;

    int tx = threadIdx.x, ty = threadIdx.y;   // 32 x 8
    if (ty == 0) {
        int lane = tx;
        float t = -1e30f;
        if (lane < EE) {
            float s = 0.f;
            #pragma unroll
            for (int j = 0; j < EMBW; j++) s += emb[lane * EMBW + j] * Wg[DD + j];
            t = s;
        }
        float best = -1e30f, second = -1e30f;
        int be = 0, se = 0;
        #pragma unroll
        for (int e = 0; e < EE; e++) {
            float te = __shfl_sync(0xFFFFFFFFu, t, e);
            if (te > best)        { second = best; se = be; best = te; be = e; }
            else if (te > second) { second = te; se = e; }
        }
        if (lane == 0) {
            float e2 = expf(second - best);
            float inv = 1.0f / (1.0f + e2);
            s_g1 = inv;
            s_g2 = e2 * inv;
            s_e1 = be;
            s_e2 = se;
        }
    }
    __syncthreads();

    int s0 = blockIdx.x * 32, d0 = blockIdx.y * 32;
    float g1 = s_g1, g2 = s_g2;
    const float* A1 = We + (size_t)s_e1 * SS * DD;
    const float* A2 = We + (size_t)s_e2 * SS * DD;
    #pragma unroll
    for (int i = 0; i < 4; i++) {
        int s = s0 + ty + i * 8;
        tile[ty + i * 8][tx] =
            g1 * A1[(size_t)s * DD + d0 + tx] + g2 * A2[(size_t)s * DD + d0 + tx];
    }
    __syncthreads();
    #pragma unroll
    for (int i = 0; i < 4; i++) {
        int d = d0 + ty + i * 8;
        g_Ah[(size_t)d * SS + s0 + tx] = __float2half_rn(tile[tx][ty + i * 8]);
    }
}

// ---------------------------------------------------------------------------
// K2: prep_x — R7 byte-exact: fused exact median (1-bit radix select) +
// subtract + fp16 convert + K-major transpose.  Block = (b, half of 32
// channels), 16 warps, 1 warp/channel.
// ---------------------------------------------------------------------------
__global__ void __launch_bounds__(512) prep_x(const float* __restrict__ x) {
    __shared__ float sm[16 * 513];
    int b = blockIdx.x >> 1;
    int half = blockIdx.x & 1;
    const float4* xb4 = (const float4*)(x + (size_t)b * SS * CC + half * 16);

    for (int i = threadIdx.x; i < 512 * 4; i += 512) {
        int s = i >> 2, q = i & 3;
        float4 v = xb4[s * 8 + q];
        sm[(q * 4 + 0) * 513 + s] = v.x;
        sm[(q * 4 + 1) * 513 + s] = v.y;
        sm[(q * 4 + 2) * 513 + s] = v.z;
        sm[(q * 4 + 3) * 513 + s] = v.w;
    }
    __syncthreads();

    int w = threadIdx.x >> 5;
    int lane = threadIdx.x & 31;

    unsigned u[16];
    #pragma unroll
    for (int r = 0; r < 16; r++)
        u[r] = f2ord(sm[w * 513 + lane + 32 * r]);

    // 1-bit radix select: order stat 255 (0-indexed) among 512
    unsigned active = 0xFFFFu;
    int k = 255, na = 512;
    for (int bit = 31; bit >= 0; bit--) {
        unsigned m0 = 0;
        #pragma unroll
        for (int r = 0; r < 16; r++)
            m0 |= ((((u[r] >> bit) & 1u) ^ 1u) << r);
        m0 &= active;
        int tot0 = __reduce_add_sync(0xFFFFFFFFu, __popc(m0));
        if (k < tot0) { active = m0; na = tot0; }
        else          { k -= tot0; active &= ~m0; na -= tot0; }
        if (na == 1) break;
    }
    unsigned cand = 0;
    #pragma unroll
    for (int r = 0; r < 16; r++)
        if ((active >> r) & 1u) cand = u[r];
    unsigned v1 = __reduce_max_sync(0xFFFFFFFFu, cand);

    // order stat 256: count(<= v1) >= 257 ? v1 : min of > v1
    int le = 0;
    unsigned gtmin = 0xFFFFFFFFu;
    #pragma unroll
    for (int r = 0; r < 16; r++) {
        le += (u[r] <= v1) ? 1 : 0;
        if (u[r] > v1 && u[r] < gtmin) gtmin = u[r];
    }
    int totle = __reduce_add_sync(0xFFFFFFFFu, le);
    unsigned mn = __reduce_min_sync(0xFFFFFFFFu, gtmin);
    unsigned v2 = (totle >= 257) ? v1 : mn;
    float med = 0.5f * (ord2f(v1) + ord2f(v2));

    int c = half * 16 + w;
    __half* dsth = g_Xh + (size_t)(b * CC + c) * SS;
    #pragma unroll
    for (int r = 0; r < 8; r++) {
        int s = r * 64 + lane * 2;
        float a0 = sm[w * 513 + s]     - med;
        float a1 = sm[w * 513 + s + 1] - med;
        *reinterpret_cast<__half2*>(dsth + s) = __floats2half2_rn(a0, a1);
    }
}

// ---------------------------------------------------------------------------
// K3: single-pass fp16 mma.sync GEMM — byte-exact R7/R12 configuration
// (measured 39.3-39.8 us).  Grid = 128 CTAs (4 m-tiles x 32 n-groups),
// 256 thr (8 warps), warp 32x64, KC=64, 4-stage cp.async pipeline,
// prefetch distance 3, continuous stream across the CTA's 4 n-tiles.
// ---------------------------------------------------------------------------
#define CTA_M 128
#define CTA_N 128
#define KC 64
#define NCH (SS / KC)            // 8 chunks per n-tile
#define NTPC 4                   // n-tiles per CTA
#define NIT (NTPC * NCH)         // 32 flat iterations
#define STG_BYTES 32768          // Ah 16K | Bh 16K
#define OFF_AH 0
#define OFF_BH 16384
#define NSTG 4
#define GSMEM (NSTG * STG_BYTES) // 131072

__global__ void __launch_bounds__(256) gemm_kernel(float* __restrict__ out) {
    extern __shared__ char smem[];
    uint32_t sb = smem_u32(smem);
    int tid = threadIdx.x;
    int lane = tid & 31, wid = tid >> 5;
    int wm = wid & 3;            // 4 m-groups of 32
    int wn = wid >> 2;           // 2 n-groups of 64
    int m0 = (blockIdx.x & 3) * CTA_M;
    int ng = blockIdx.x >> 2;    // n-group: tiles ng*4 .. ng*4+3

    const char* gA = (const char*)(g_Ah + (size_t)m0 * SS);
    const char* gB = (const char*)g_Xh;

    auto ldchunk = [&](int stage, int it) {
        uint32_t tb = sb + stage * STG_BYTES;
        int u = it >> 3, ck = it & 7;
        size_t nrow0 = (size_t)(ng * NTPC + u) * CTA_N;
        size_t kb = (size_t)ck * (KC * 2);
        #pragma unroll
        for (int t = 0; t < 4; t++) {
            int idx = tid + t * 256;
            int r = idx >> 3, c = idx & 7;
            uint32_t so = (uint32_t)(r * 128 + ((c * 16) ^ ((r & 7) << 4)));
            size_t goA = (size_t)r * (SS * 2) + kb + c * 16;
            size_t goB = (nrow0 + r) * (SS * 2) + kb + c * 16;
            cp_async16(tb + OFF_AH + so, gA + goA);
            cp_async16(tb + OFF_BH + so, gB + goB);
        }
        asm volatile("cp.async.commit_group;" ::: "memory");
    };

    ldchunk(0, 0);
    ldchunk(1, 1);
    ldchunk(2, 2);

    float acc[2][8][4];
    int r8 = lane & 7;
    int half8 = ((lane >> 3) & 1) * 8;
    int kh16 = (lane >> 4) * 16;

    for (int it = 0; it < NIT; it++) {
        // group for 'it' complete; it+1, it+2 may remain outstanding
        asm volatile("cp.async.wait_group 2;" ::: "memory");
        __syncthreads();

        // stage (it+3)%4 == (it-1)%4 is free after the sync above
        if (it + 3 < NIT) ldchunk((it + 3) % NSTG, it + 3);
        else asm volatile("cp.async.commit_group;" ::: "memory");

        if ((it & 7) == 0) {
            #pragma unroll
            for (int i = 0; i < 2; i++)
                #pragma unroll
                for (int j = 0; j < 8; j++)
                    #pragma unroll
                    for (int q = 0; q < 4; q++) acc[i][j][q] = 0.f;
        }

        uint32_t tb = sb + (it % NSTG) * STG_BYTES;
        #pragma unroll
        for (int ks = 0; ks < 4; ks++) {
            int kb0 = ks * 32 + kh16;
            uint32_t a[2][4], bfr[4][4];
            #pragma unroll
            for (int mb = 0; mb < 2; mb++) {
                int row = wm * 32 + mb * 16 + half8 + r8;
                uint32_t ad = (uint32_t)(row * 128 + (kb0 ^ ((row & 7) << 4)));
                ldsm4(a[mb], tb + OFF_AH + ad);
            }
            #pragma unroll
            for (int nb2 = 0; nb2 < 4; nb2++) {
                int row = wn * 64 + nb2 * 16 + half8 + r8;
                uint32_t ad = (uint32_t)(row * 128 + (kb0 ^ ((row & 7) << 4)));
                ldsm4(bfr[nb2], tb + OFF_BH + ad);
            }
            #pragma unroll
            for (int mb = 0; mb < 2; mb++)
                #pragma unroll
                for (int nb2 = 0; nb2 < 4; nb2++)
                    #pragma unroll
                    for (int s = 0; s < 2; s++)
                        mma_fp16(acc[mb][nb2 * 2 + s], a[mb],
                                 bfr[nb2][s], bfr[nb2][s + 2]);
        }

        if ((it & 7) == 7) {
            int u = it >> 3;
            int nbase = (ng * NTPC + u) * CTA_N + wn * 64;
            #pragma unroll
            for (int mb = 0; mb < 2; mb++) {
                int dr = m0 + wm * 32 + mb * 16 + (lane >> 2);
                #pragma unroll
                for (int nb8 = 0; nb8 < 8; nb8++) {
                    int bidx = (nbase >> 5) + (nb8 >> 2);
                    int v = (nb8 & 3) * 8 + 2 * (lane & 3);
                    float* ob = out + (size_t)bidx * DD * CC;
                    *(float2*)(ob + (size_t)dr * CC + v) =
                        make_float2(acc[mb][nb8][0], acc[mb][nb8][1]);
                    *(float2*)(ob + (size_t)(dr + 8) * CC + v) =
                        make_float2(acc[mb][nb8][2], acc[mb][nb8][3]);
                }
            }
        }
    }
}

// ---------------------------------------------------------------------------
// Launch.  Inputs: x, Wp, bp, emb, Wg, bg, We, k  (Wp/bp/bg/k provably unused)
// ---------------------------------------------------------------------------
extern "C" void kernel_launch(void* const* d_in, const int* in_sizes, int n_in,
                              void* d_out, int out_size) {
    const float* x   = (const float*)d_in[0];
    const float* emb = (const float*)d_in[3];
    const float* Wg  = (const float*)d_in[4];
    const float* We  = (const float*)d_in[6];
    float* out = (float*)d_out;

    cudaFuncSetAttribute(gemm_kernel,
                         cudaFuncAttributeMaxDynamicSharedMemorySize, GSMEM);

    prep_w<<<dim3(16, 16), dim3(32, 8)>>>(We, emb, Wg);
    prep_x<<<BB * 2, 512>>>(x);
    gemm_kernel<<<128, 256, GSMEM>>>(out);
}

// round 16
// speedup vs baseline: 1.5050x; 1.0961x over previous
#include <cuda_runtime.h>
#include <cuda_fp16.h>
#include <cstdint>

// Problem constants
#define BB 512
#define SS 512
#define CC 32
#define DD 512
#define EE 8
#define EMBW 32

// ---------------------------------------------------------------------------
// Scratch (device globals — no allocation allowed)
// ---------------------------------------------------------------------------
__device__ __half g_Ah[DD * SS];        // Wmix^T fp16  [d][s] K-major
__device__ __half g_Xh[BB * CC * SS];   // xn fp16 [n=(b,v)][s] K-major

// ---------------------------------------------------------------------------
// helpers
// ---------------------------------------------------------------------------
__device__ __forceinline__ uint32_t smem_u32(const void* p) {
    uint32_t a;
    asm("{ .reg .u64 t; cvta.to.shared.u64 t, %1; cvt.u32.u64 %0, t; }"
        : "=r"(a) : "l"(p));
    return a;
}
__device__ __forceinline__ void cp_async16(uint32_t dst_smem, const void* src) {
    asm volatile("cp.async.cg.shared.global [%0], [%1], 16;"
                 :: "r"(dst_smem), "l"(src));
}
__device__ __forceinline__ void ldsm4(uint32_t* r, uint32_t addr) {
    asm volatile("ldmatrix.sync.aligned.m8n8.x4.shared.b16 {%0,%1,%2,%3}, [%4];"
                 : "=r"(r[0]), "=r"(r[1]), "=r"(r[2]), "=r"(r[3]) : "r"(addr));
}
__device__ __forceinline__ void mma_fp16(float* d, const uint32_t* a,
                                         uint32_t b0, uint32_t b1) {
    asm volatile(
        "mma.sync.aligned.m16n8k16.row.col.f32.f16.f16.f32 "
        "{%0,%1,%2,%3}, {%4,%5,%6,%7}, {%8,%9}, {%0,%1,%2,%3};"
        : "+f"(d[0]), "+f"(d[1]), "+f"(d[2]), "+f"(d[3])
        : "r"(a[0]), "r"(a[1]), "r"(a[2]), "r"(a[3]), "r"(b0), "r"(b1));
}
__device__ __forceinline__ unsigned f2ord(float f) {
    unsigned raw = __float_as_uint(f);
    return (raw & 0x80000000u) ? ~raw : (raw | 0x80000000u);
}
__device__ __forceinline__ float ord2f(unsigned u) {
    return (u & 0x80000000u) ? __uint_as_float(u ^ 0x80000000u)
                             : __uint_as_float(~u);
}

// ---------------------------------------------------------------------------
// K1: prep_w — gate inline, A[d][s] = g1*We[e1][s][d] + g2*We[e2][s][d],
// fp16, K-major.  32x32 smem transpose tiles.  (Measured 6.0-6.2 us.)
// ---------------------------------------------------------------------------
__global__ void prep_w(const float* __restrict__ We,
                       const float* __restrict__ emb,
                       const float* __restrict__ Wg) {
    __shared__ float tile[32][33];
    __shared__ float s_g1, s_g2;
    __shared__ int s_e1, s_e2;

    int tx = threadIdx.x, ty = threadIdx.y;   // 32 x 8
    if (ty == 0) {
        int lane = tx;
        float t = -1e30f;
        if (lane < EE) {
            float s = 0.f;
            #pragma unroll
            for (int j = 0; j < EMBW; j++) s += emb[lane * EMBW + j] * Wg[DD + j];
            t = s;
        }
        float best = -1e30f, second = -1e30f;
        int be = 0, se = 0;
        #pragma unroll
        for (int e = 0; e < EE; e++) {
            float te = __shfl_sync(0xFFFFFFFFu, t, e);
            if (te > best)        { second = best; se = be; best = te; be = e; }
            else if (te > second) { second = te; se = e; }
        }
        if (lane == 0) {
            float e2 = expf(second - best);
            float inv = 1.0f / (1.0f + e2);
            s_g1 = inv;
            s_g2 = e2 * inv;
            s_e1 = be;
            s_e2 = se;
        }
    }
    __syncthreads();

    int s0 = blockIdx.x * 32, d0 = blockIdx.y * 32;
    float g1 = s_g1, g2 = s_g2;
    const float* A1 = We + (size_t)s_e1 * SS * DD;
    const float* A2 = We + (size_t)s_e2 * SS * DD;
    #pragma unroll
    for (int i = 0; i < 4; i++) {
        int s = s0 + ty + i * 8;
        tile[ty + i * 8][tx] =
            g1 * A1[(size_t)s * DD + d0 + tx] + g2 * A2[(size_t)s * DD + d0 + tx];
    }
    __syncthreads();
    #pragma unroll
    for (int i = 0; i < 4; i++) {
        int d = d0 + ty + i * 8;
        g_Ah[(size_t)d * SS + s0 + tx] = __float2half_rn(tile[tx][ty + i * 8]);
    }
}

// ---------------------------------------------------------------------------
// K2: prep_x — R7 byte-exact: fused exact median (1-bit radix select) +
// subtract + fp16 convert + K-major transpose.  Block = (b, half of 32
// channels), 16 warps, 1 warp/channel.
// ---------------------------------------------------------------------------
__global__ void __launch_bounds__(512) prep_x(const float* __restrict__ x) {
    __shared__ float sm[16 * 513];
    int b = blockIdx.x >> 1;
    int half = blockIdx.x & 1;
    const float4* xb4 = (const float4*)(x + (size_t)b * SS * CC + half * 16);

    for (int i = threadIdx.x; i < 512 * 4; i += 512) {
        int s = i >> 2, q = i & 3;
        float4 v = xb4[s * 8 + q];
        sm[(q * 4 + 0) * 513 + s] = v.x;
        sm[(q * 4 + 1) * 513 + s] = v.y;
        sm[(q * 4 + 2) * 513 + s] = v.z;
        sm[(q * 4 + 3) * 513 + s] = v.w;
    }
    __syncthreads();

    int w = threadIdx.x >> 5;
    int lane = threadIdx.x & 31;

    unsigned u[16];
    #pragma unroll
    for (int r = 0; r < 16; r++)
        u[r] = f2ord(sm[w * 513 + lane + 32 * r]);

    // 1-bit radix select: order stat 255 (0-indexed) among 512
    unsigned active = 0xFFFFu;
    int k = 255, na = 512;
    for (int bit = 31; bit >= 0; bit--) {
        unsigned m0 = 0;
        #pragma unroll
        for (int r = 0; r < 16; r++)
            m0 |= ((((u[r] >> bit) & 1u) ^ 1u) << r);
        m0 &= active;
        int tot0 = __reduce_add_sync(0xFFFFFFFFu, __popc(m0));
        if (k < tot0) { active = m0; na = tot0; }
        else          { k -= tot0; active &= ~m0; na -= tot0; }
        if (na == 1) break;
    }
    unsigned cand = 0;
    #pragma unroll
    for (int r = 0; r < 16; r++)
        if ((active >> r) & 1u) cand = u[r];
    unsigned v1 = __reduce_max_sync(0xFFFFFFFFu, cand);

    // order stat 256: count(<= v1) >= 257 ? v1 : min of > v1
    int le = 0;
    unsigned gtmin = 0xFFFFFFFFu;
    #pragma unroll
    for (int r = 0; r < 16; r++) {
        le += (u[r] <= v1) ? 1 : 0;
        if (u[r] > v1 && u[r] < gtmin) gtmin = u[r];
    }
    int totle = __reduce_add_sync(0xFFFFFFFFu, le);
    unsigned mn = __reduce_min_sync(0xFFFFFFFFu, gtmin);
    unsigned v2 = (totle >= 257) ? v1 : mn;
    float med = 0.5f * (ord2f(v1) + ord2f(v2));

    int c = half * 16 + w;
    __half* dsth = g_Xh + (size_t)(b * CC + c) * SS;
    #pragma unroll
    for (int r = 0; r < 8; r++) {
        int s = r * 64 + lane * 2;
        float a0 = sm[w * 513 + s]     - med;
        float a1 = sm[w * 513 + s + 1] - med;
        *reinterpret_cast<__half2*>(dsth + s) = __floats2half2_rn(a0, a1);
    }
}

// ---------------------------------------------------------------------------
// K3: single-pass fp16 mma.sync GEMM.  Clean warp-count experiment:
// 16 warps (4/SMSP) x the PROVEN 32x64 warp tile x the PROVEN 4-stage /
// prefetch-3 pipeline.  CTA tile 128x256 (wm in 4 x wn in 4), stage 48 KB,
// 192 KB smem, 1 CTA/SM, NTPC=2 -> NIT=16, grid 128.
// Per-warp instruction mix is byte-identical to R7; only warps/SMSP 2->4.
// ---------------------------------------------------------------------------
#define CTA_M 128
#define CTA_N 256
#define KC 64
#define NCH (SS / KC)            // 8 chunks per n-tile
#define NTPC 2                   // n-tiles (of 256) per CTA
#define NIT (NTPC * NCH)         // 16 flat iterations
#define STG_BYTES 49152          // Ah 16K | Bh 32K
#define OFF_AH 0
#define OFF_BH 16384
#define NSTG 4
#define GSMEM (NSTG * STG_BYTES) // 196608

__global__ void __launch_bounds__(512) gemm_kernel(float* __restrict__ out) {
    extern __shared__ char smem[];
    uint32_t sb = smem_u32(smem);
    int tid = threadIdx.x;
    int lane = tid & 31, wid = tid >> 5;
    int wm = wid & 3;            // 4 m-groups of 32
    int wn = wid >> 2;           // 4 n-groups of 64
    int m0 = (blockIdx.x & 3) * CTA_M;
    int ng = blockIdx.x >> 2;    // n-group: 256-wide tiles ng*2 .. ng*2+1

    const char* gA = (const char*)(g_Ah + (size_t)m0 * SS);
    const char* gB = (const char*)g_Xh;

    auto ldchunk = [&](int stage, int it) {
        uint32_t tb = sb + stage * STG_BYTES;
        int u = it >> 3, ck = it & 7;
        size_t nrow0 = (size_t)(ng * NTPC + u) * CTA_N;
        size_t kb = (size_t)ck * (KC * 2);
        // A: 128 rows x 8 float4 = 1024
        #pragma unroll
        for (int t = 0; t < 2; t++) {
            int idx = tid + t * 512;
            int r = idx >> 3, c = idx & 7;
            uint32_t so = (uint32_t)(r * 128 + ((c * 16) ^ ((r & 7) << 4)));
            cp_async16(tb + OFF_AH + so,
                       gA + (size_t)r * (SS * 2) + kb + c * 16);
        }
        // B: 256 rows x 8 float4 = 2048
        #pragma unroll
        for (int t = 0; t < 4; t++) {
            int idx = tid + t * 512;
            int r = idx >> 3, c = idx & 7;
            uint32_t so = (uint32_t)(r * 128 + ((c * 16) ^ ((r & 7) << 4)));
            cp_async16(tb + OFF_BH + so,
                       gB + (nrow0 + r) * (SS * 2) + kb + c * 16);
        }
        asm volatile("cp.async.commit_group;" ::: "memory");
    };

    ldchunk(0, 0);
    ldchunk(1, 1);
    ldchunk(2, 2);

    float acc[2][8][4];
    int r8 = lane & 7;
    int half8 = ((lane >> 3) & 1) * 8;
    int kh16 = (lane >> 4) * 16;

    for (int it = 0; it < NIT; it++) {
        // group for 'it' complete; it+1, it+2 may remain outstanding
        asm volatile("cp.async.wait_group 2;" ::: "memory");
        __syncthreads();

        // stage (it+3)%4 == (it-1)%4 is free after the sync above
        if (it + 3 < NIT) ldchunk((it + 3) % NSTG, it + 3);
        else asm volatile("cp.async.commit_group;" ::: "memory");

        if ((it & 7) == 0) {
            #pragma unroll
            for (int i = 0; i < 2; i++)
                #pragma unroll
                for (int j = 0; j < 8; j++)
                    #pragma unroll
                    for (int q = 0; q < 4; q++) acc[i][j][q] = 0.f;
        }

        uint32_t tb = sb + (it % NSTG) * STG_BYTES;
        #pragma unroll
        for (int ks = 0; ks < 4; ks++) {
            int kb0 = ks * 32 + kh16;
            uint32_t a[2][4], bfr[4][4];
            #pragma unroll
            for (int mb = 0; mb < 2; mb++) {
                int row = wm * 32 + mb * 16 + half8 + r8;
                uint32_t ad = (uint32_t)(row * 128 + (kb0 ^ ((row & 7) << 4)));
                ldsm4(a[mb], tb + OFF_AH + ad);
            }
            #pragma unroll
            for (int nb2 = 0; nb2 < 4; nb2++) {
                int row = wn * 64 + nb2 * 16 + half8 + r8;
                uint32_t ad = (uint32_t)(row * 128 + (kb0 ^ ((row & 7) << 4)));
                ldsm4(bfr[nb2], tb + OFF_BH + ad);
            }
            #pragma unroll
            for (int mb = 0; mb < 2; mb++)
                #pragma unroll
                for (int nb2 = 0; nb2 < 4; nb2++)
                    #pragma unroll
                    for (int s = 0; s < 2; s++)
                        mma_fp16(acc[mb][nb2 * 2 + s], a[mb],
                                 bfr[nb2][s], bfr[nb2][s + 2]);
        }

        if ((it & 7) == 7) {
            // store n-tile: warp covers n in [wn*64, wn*64+64) = 2 batch rows
            int u = it >> 3;
            int nbase = (ng * NTPC + u) * CTA_N + wn * 64;
            #pragma unroll
            for (int mb = 0; mb < 2; mb++) {
                int dr = m0 + wm * 32 + mb * 16 + (lane >> 2);
                #pragma unroll
                for (int nb8 = 0; nb8 < 8; nb8++) {
                    int bidx = (nbase >> 5) + (nb8 >> 2);
                    int v = (nb8 & 3) * 8 + 2 * (lane & 3);
                    float* ob = out + (size_t)bidx * DD * CC;
                    *(float2*)(ob + (size_t)dr * CC + v) =
                        make_float2(acc[mb][nb8][0], acc[mb][nb8][1]);
                    *(float2*)(ob + (size_t)(dr + 8) * CC + v) =
                        make_float2(acc[mb][nb8][2], acc[mb][nb8][3]);
                }
            }
        }
    }
}

// ---------------------------------------------------------------------------
// Launch.  Inputs: x, Wp, bp, emb, Wg, bg, We, k  (Wp/bp/bg/k provably unused)
// ---------------------------------------------------------------------------
extern "C" void kernel_launch(void* const* d_in, const int* in_sizes, int n_in,
                              void* d_out, int out_size) {
    const float* x   = (const float*)d_in[0];
    const float* emb = (const float*)d_in[3];
    const float* Wg  = (const float*)d_in[4];
    const float* We  = (const float*)d_in[6];
    float* out = (float*)d_out;

    cudaFuncSetAttribute(gemm_kernel,
                         cudaFuncAttributeMaxDynamicSharedMemorySize, GSMEM);

    prep_w<<<dim3(16, 16), dim3(32, 8)>>>(We, emb, Wg);
    prep_x<<<BB * 2, 512>>>(x);
    gemm_kernel<<<128, 512, GSMEM>>>(out);
}